// round 2
// baseline (speedup 1.0000x reference)
#include <cuda_runtime.h>
#include <cstdint>

// Problem sizes (fixed by the reference)
#define NN    4096
#define INF   512
#define OUTF  512

// GEMM tiling
#define BM 128
#define BN 128
#define BK 32
#define STAGES 3
#define GTHREADS 256

// SMEM geometry: rows padded to 36 floats (144 B) for conflict-free fragment LDS
#define ROWF   36
#define TILEF  (128 * ROWF)              // floats per operand tile
#define STAGEF (2 * TILEF)               // floats per stage (A + B)
#define STAGE_BYTES (STAGEF * 4)         // 36864 B
#define SMEM_TOTAL (STAGES * STAGE_BYTES)  // 110592 B

// Scratch (allocation-free rule: __device__ globals)
__device__ float g_A[(size_t)NN * NN];      // 64 MB dense adjacency (tf32-rounded)
__device__ float g_ST[(size_t)OUTF * NN];   // support^T [512][4096], K-major for GEMM2 B (tf32-rounded)
__device__ float g_Wt[(size_t)OUTF * INF];  // W^T [512][512]

// ---------------- helpers ----------------

__device__ __forceinline__ uint32_t smem_u32(const void* p) {
    uint32_t a;
    asm("{ .reg .u64 t; cvta.to.shared.u64 t, %1; cvt.u32.u64 %0, t; }" : "=r"(a) : "l"(p));
    return a;
}

__device__ __forceinline__ float f2tf_f(float x) {  // round-to-nearest tf32, returned as float
    uint32_t r;
    asm("cvt.rna.tf32.f32 %0, %1;" : "=r"(r) : "f"(x));
    return __uint_as_float(r);
}

__device__ __forceinline__ uint32_t f2tf_u(float x) {
    uint32_t r;
    asm("cvt.rna.tf32.f32 %0, %1;" : "=r"(r) : "f"(x));
    return r;
}

__device__ __forceinline__ void cp16(uint32_t saddr, const void* g) {
    asm volatile("cp.async.cg.shared.global [%0], [%1], 16;" :: "r"(saddr), "l"(g) : "memory");
}
#define CP_COMMIT() asm volatile("cp.async.commit_group;" ::: "memory")
#define CP_WAIT(n)  asm volatile("cp.async.wait_group %0;" :: "n"(n) : "memory")

__device__ __forceinline__ void mma1688(float* c, const uint32_t* a, const uint32_t* b) {
    asm volatile(
        "mma.sync.aligned.m16n8k8.row.col.f32.tf32.tf32.f32 "
        "{%0,%1,%2,%3}, {%4,%5,%6,%7}, {%8,%9}, {%0,%1,%2,%3};"
        : "+f"(c[0]), "+f"(c[1]), "+f"(c[2]), "+f"(c[3])
        : "r"(a[0]), "r"(a[1]), "r"(a[2]), "r"(a[3]), "r"(b[0]), "r"(b[1]));
}

// ---------------- Kernel 1: W^T ----------------
__global__ void transposeW(const float* __restrict__ W, float* __restrict__ Wt) {
    __shared__ float t[32][33];
    int bx = blockIdx.x * 32, by = blockIdx.y * 32;  // bx: o, by: c
    int x = threadIdx.x, y = threadIdx.y;
#pragma unroll
    for (int j = 0; j < 32; j += 8)
        t[y + j][x] = W[(size_t)(by + y + j) * OUTF + bx + x];
    __syncthreads();
#pragma unroll
    for (int j = 0; j < 32; j += 8)
        Wt[(size_t)(bx + y + j) * INF + by + x] = t[x][y + j];
}

// ---------------- Kernel 2: A = reshape(E @ wq), rounded to tf32 ----------------
__global__ void __launch_bounds__(256) edgeA(const float4* __restrict__ E,
                                             const float* __restrict__ wq,
                                             float* __restrict__ Aout) {
    size_t i = (size_t)blockIdx.x * blockDim.x + threadIdx.x;
    float w0 = __ldg(wq + 0), w1 = __ldg(wq + 1), w2 = __ldg(wq + 2), w3 = __ldg(wq + 3);
    size_t base = i * 4;
    float4 e0 = E[base + 0], e1 = E[base + 1], e2 = E[base + 2], e3 = E[base + 3];
    float4 o;
    o.x = f2tf_f(e0.x * w0 + e0.y * w1 + e0.z * w2 + e0.w * w3);
    o.y = f2tf_f(e1.x * w0 + e1.y * w1 + e1.z * w2 + e1.w * w3);
    o.z = f2tf_f(e2.x * w0 + e2.y * w1 + e2.z * w2 + e2.w * w3);
    o.w = f2tf_f(e3.x * w0 + e3.y * w1 + e3.z * w2 + e3.w * w3);
    *reinterpret_cast<float4*>(Aout + base) = o;
}

// ---------------- GEMM: C[M,N] = A[M,K] * B[N,K]^T (+bias), tf32 mma.sync ----------------
// A row-major K-major, B row-major K-major. 128x128x32 tiles, 3-stage cp.async.
// 8 warps: wm = wid&1 (2 M-warps of 64), wn = wid>>1 (4 N-warps of 32).
// CONV: cvt operands to tf32 in-fragment; ROUND_OUT: round C to tf32 before store.
template <bool CONV, bool ROUND_OUT>
__global__ void __launch_bounds__(GTHREADS, 1)
gemm_mma(const float* __restrict__ A, const float* __restrict__ B,
         float* __restrict__ C, const float* __restrict__ bias,
         int M, int N, int K) {
    extern __shared__ float smem[];
    const uint32_t sb = smem_u32(smem);
    const int tid = threadIdx.x;
    const int wid = tid >> 5;
    const int lid = tid & 31;
    const int gid = lid >> 2;   // group id (0..7)
    const int tig = lid & 3;    // thread-in-group
    const int wm = wid & 1;     // 0..1
    const int wn = wid >> 1;    // 0..3
    const int n0 = blockIdx.x * BN;
    const int m0 = blockIdx.y * BM;

    const int nch = K / BK;

    // ---- tile loader: chunk ch -> stage s ----
    auto load_tiles = [&](int s, int ch) {
        const int k0 = ch * BK;
        const uint32_t sbase = sb + (uint32_t)s * STAGE_BYTES;
#pragma unroll
        for (int i = 0; i < 4; i++) {
            int chid = tid + i * GTHREADS;   // 0..1023
            int row = chid >> 3;             // 0..127
            int off = (chid & 7) << 2;       // float offset 0..28
            cp16(sbase + (uint32_t)(row * 144 + off * 4),
                 A + (size_t)(m0 + row) * K + k0 + off);
            cp16(sbase + (uint32_t)(TILEF * 4 + row * 144 + off * 4),
                 B + (size_t)(n0 + row) * K + k0 + off);
        }
    };

    // prologue: stages 0..STAGES-2
#pragma unroll
    for (int s = 0; s < STAGES - 1; s++) {
        load_tiles(s, s);
        CP_COMMIT();
    }

    float acc[4][4][4];
#pragma unroll
    for (int mt = 0; mt < 4; mt++)
#pragma unroll
        for (int nt = 0; nt < 4; nt++)
#pragma unroll
            for (int j = 0; j < 4; j++) acc[mt][nt][j] = 0.0f;

    for (int ch = 0; ch < nch; ++ch) {
        CP_WAIT(STAGES - 2);
        __syncthreads();

        // prefetch chunk ch+STAGES-1 into stage (ch-1)%STAGES (just-freed stage)
        int pf = ch + STAGES - 1;
        if (pf < nch) load_tiles(pf % STAGES, pf);
        CP_COMMIT();

        // compute on stage ch%STAGES
        const float* As = smem + (ch % STAGES) * STAGEF + (wm * 64 + gid) * ROWF + tig;
        const float* Bs = smem + (ch % STAGES) * STAGEF + TILEF + (wn * 32 + gid) * ROWF + tig;
#pragma unroll
        for (int ks = 0; ks < 4; ks++) {
            const int k0 = ks * 8;
            uint32_t af[4][4];
#pragma unroll
            for (int mt = 0; mt < 4; mt++) {
                const float* p = As + mt * 16 * ROWF + k0;
                af[mt][0] = __float_as_uint(p[0]);
                af[mt][1] = __float_as_uint(p[8 * ROWF]);
                af[mt][2] = __float_as_uint(p[4]);
                af[mt][3] = __float_as_uint(p[8 * ROWF + 4]);
                if (CONV) {
                    af[mt][0] = f2tf_u(__uint_as_float(af[mt][0]));
                    af[mt][1] = f2tf_u(__uint_as_float(af[mt][1]));
                    af[mt][2] = f2tf_u(__uint_as_float(af[mt][2]));
                    af[mt][3] = f2tf_u(__uint_as_float(af[mt][3]));
                }
            }
            uint32_t bf[4][2];
#pragma unroll
            for (int nt = 0; nt < 4; nt++) {
                const float* p = Bs + nt * 8 * ROWF + k0;
                bf[nt][0] = __float_as_uint(p[0]);
                bf[nt][1] = __float_as_uint(p[4]);
                if (CONV) {
                    bf[nt][0] = f2tf_u(__uint_as_float(bf[nt][0]));
                    bf[nt][1] = f2tf_u(__uint_as_float(bf[nt][1]));
                }
            }
#pragma unroll
            for (int mt = 0; mt < 4; mt++)
#pragma unroll
                for (int nt = 0; nt < 4; nt++)
                    mma1688(acc[mt][nt], af[mt], bf[nt]);
        }
    }

    // ---- epilogue ----
#pragma unroll
    for (int mt = 0; mt < 4; mt++) {
        const int r0 = m0 + wm * 64 + mt * 16 + gid;
        const int r1 = r0 + 8;
#pragma unroll
        for (int nt = 0; nt < 4; nt++) {
            const int col = n0 + wn * 32 + nt * 8 + 2 * tig;
            float b0 = 0.f, b1 = 0.f;
            if (bias) { b0 = bias[col]; b1 = bias[col + 1]; }
            float2 v0, v1;
            v0.x = acc[mt][nt][0] + b0; v0.y = acc[mt][nt][1] + b1;
            v1.x = acc[mt][nt][2] + b0; v1.y = acc[mt][nt][3] + b1;
            if (ROUND_OUT) {
                v0.x = f2tf_f(v0.x); v0.y = f2tf_f(v0.y);
                v1.x = f2tf_f(v1.x); v1.y = f2tf_f(v1.y);
            }
            *reinterpret_cast<float2*>(C + (size_t)r0 * N + col) = v0;
            *reinterpret_cast<float2*>(C + (size_t)r1 * N + col) = v1;
        }
    }
}

// ---------------- Launch ----------------
extern "C" void kernel_launch(void* const* d_in, const int* in_sizes, int n_in,
                              void* d_out, int out_size) {
    const float* X    = (const float*)d_in[0];
    // d_in[1] = adj (unused by forward)
    const float* E    = (const float*)d_in[2];
    const float* W    = (const float*)d_in[3];
    const float* wq   = (const float*)d_in[4];
    const float* bias = (const float*)d_in[5];
    float* out = (float*)d_out;

    float *pA, *pST, *pWt;
    cudaGetSymbolAddress((void**)&pA, g_A);
    cudaGetSymbolAddress((void**)&pST, g_ST);
    cudaGetSymbolAddress((void**)&pWt, g_Wt);

    cudaFuncSetAttribute(gemm_mma<true, true>,
                         cudaFuncAttributeMaxDynamicSharedMemorySize, SMEM_TOTAL);
    cudaFuncSetAttribute(gemm_mma<false, false>,
                         cudaFuncAttributeMaxDynamicSharedMemorySize, SMEM_TOTAL);

    // 1) Wt = W^T (512x512)
    transposeW<<<dim3(OUTF / 32, INF / 32), dim3(32, 8)>>>(W, pWt);

    // 2) A = tf32(reshape(E @ wq)) : 16.7M elements, 4 per thread
    edgeA<<<(NN * (size_t)NN) / (4 * 256), 256>>>((const float4*)E, wq, pA);

    // 3) S^T = W^T @ X^T : M=512(o), N=4096(i), K=512(c). A=Wt, B=X. Output K-major for step 4.
    gemm_mma<true, true><<<dim3(NN / BN, OUTF / BM), GTHREADS, SMEM_TOTAL>>>(
        pWt, X, pST, nullptr, OUTF, NN, INF);

    // 4) out = A @ S + bias : M=4096(i), N=512(o), K=4096(j). A=g_A (tf32), B=S^T (tf32).
    gemm_mma<false, false><<<dim3(OUTF / BN, NN / BM), GTHREADS, SMEM_TOTAL>>>(
        pA, pST, out, bias, NN, OUTF, NN);
}